// round 16
// baseline (speedup 1.0000x reference)
#include <cuda_runtime.h>
#include <cuda_fp16.h>
#include <math.h>
#include <stdint.h>

// ---------------- problem constants ----------------
#define BATCH   8
#define CIN     64
#define CDIM    192
#define HDIM    112
#define WDIM    112
#define L       (HDIM*WDIM)          // 12544
#define TKN     (BATCH*L)            // 100352
#define WS      7
#define NWIN    49
#define NH      6
#define HD      32
#define NWTOT   2048
#define KCONV   576

typedef unsigned long long u64;

__device__ __forceinline__ uint32_t smem_u32(const void* p) {
    uint32_t a;
    asm("{ .reg .u64 t; cvta.to.shared.u64 t, %1; cvt.u32.u64 %0, t; }" : "=r"(a) : "l"(p));
    return a;
}
__device__ __forceinline__ uint32_t packh2(float x, float y) {
    __half2 h = __floats2half2_rn(x, y);
    return *(uint32_t*)&h;
}

// ---------------- warp-MMA + cp.async primitives (base ISA) ----------------
#define LDMX4(r, addr) \
    asm volatile("ldmatrix.sync.aligned.m8n8.x4.shared.b16 {%0,%1,%2,%3}, [%4];" \
        : "=r"((r)[0]), "=r"((r)[1]), "=r"((r)[2]), "=r"((r)[3]) : "r"(addr))

#define LDMX4T(r, addr) \
    asm volatile("ldmatrix.sync.aligned.m8n8.x4.trans.shared.b16 {%0,%1,%2,%3}, [%4];" \
        : "=r"((r)[0]), "=r"((r)[1]), "=r"((r)[2]), "=r"((r)[3]) : "r"(addr))

#define MMA16816(c, a, b0, b1) \
    asm volatile("mma.sync.aligned.m16n8k16.row.col.f32.f16.f16.f32 " \
        "{%0,%1,%2,%3}, {%4,%5,%6,%7}, {%8,%9}, {%0,%1,%2,%3};" \
        : "+f"((c)[0]), "+f"((c)[1]), "+f"((c)[2]), "+f"((c)[3]) \
        : "r"((a)[0]), "r"((a)[1]), "r"((a)[2]), "r"((a)[3]), "r"(b0), "r"(b1))

#define MMA16816R(c, a0, a1, a2, a3, b0, b1) \
    asm volatile("mma.sync.aligned.m16n8k16.row.col.f32.f16.f16.f32 " \
        "{%0,%1,%2,%3}, {%4,%5,%6,%7}, {%8,%9}, {%0,%1,%2,%3};" \
        : "+f"((c)[0]), "+f"((c)[1]), "+f"((c)[2]), "+f"((c)[3]) \
        : "r"(a0), "r"(a1), "r"(a2), "r"(a3), "r"(b0), "r"(b1))

#define CPA16(dst, src) \
    asm volatile("cp.async.ca.shared.global [%0], [%1], 16;" :: "r"(dst), "l"(src))
#define CPA16Z(dst, src, sz) \
    asm volatile("cp.async.ca.shared.global [%0], [%1], 16, %2;" :: "r"(dst), "l"(src), "r"(sz))
#define CPCOMMIT() asm volatile("cp.async.commit_group;" ::: "memory")
#define CPWAIT(n)  asm volatile("cp.async.wait_group %0;" :: "n"(n) : "memory")

// ---------------- scratch (static device) ----------------
__device__ __half g_xh [(size_t)TKN*CIN];       // x in NHWC fp16
__device__ __half g_ln [(size_t)TKN*CDIM];
__device__ __half g_ao [(size_t)TKN*CDIM];
__device__ __half g_m1 [(size_t)TKN*4*CDIM];
__device__ __half g_qkv[(size_t)TKN*3*CDIM];
__device__ __half g_xt [(size_t)TKN*CDIM];
__device__ __half g_t1 [(size_t)TKN*CDIM];
__device__ float g_bias[NH*64*56];
__device__ __half g_wconv[CDIM*KCONV];          // remapped: k' = (kh*3+kw)*64 + ci
__device__ __half g_wqkv [3*CDIM*CDIM];
__device__ __half g_wap  [CDIM*CDIM];
__device__ __half g_wfc1 [4*CDIM*CDIM];
__device__ __half g_wfc2 [CDIM*4*CDIM];

// ---------------- fp16 HMMA GEMM, BM=128 BN=192 BK=32, 512 thr (fp32 acc) ---------
// EPI: 3 IMPLICIT-CONV + bias->Ch + LN->Cs | 4 bias+res->Ch + LN->Cs
//      6 bias+res+res2 -> NCHW out (Cf)
#define AROWB  80
#define BROWB  80
#define ASTAGE 10240
#define BSTAGE 15360
#define STG    4
#define SMEM_GEMM (STG*(ASTAGE+BSTAGE))   // 102400
template<int EPI>
__global__ __launch_bounds__(512) void mma_gemm(
    const __half* __restrict__ A, const __half* __restrict__ B,
    const float* __restrict__ bias, const __half* __restrict__ resh,
    const __half* __restrict__ res2h, const float* __restrict__ lnw,
    const float* __restrict__ lnb,
    float* __restrict__ Cf, __half* __restrict__ Ch, __half* __restrict__ Cs,
    int N, int K)
{
    extern __shared__ __align__(16) char dsm[];
    const uint32_t s0 = smem_u32(dsm);
    const int t = threadIdx.x, wid = t >> 5, lane = t & 31;
    const int n0 = blockIdx.x * 192, m0 = blockIdx.y * 128;
    const int wm = (wid >> 2) * 32, wn = (wid & 3) * 48;
    const int mat = lane >> 3, rr = lane & 7;
    const int kc = K >> 5;

    int mb = 0, mh = 0, mw = 0;
    if (EPI == 3) {
        const int m = m0 + (t >> 2);
        mb = m / L;
        const int hw = m - mb*L;
        mh = hw / WDIM;
        mw = hw - mh*WDIM;
    }

    float acc[2][6][4];
    #pragma unroll
    for (int i = 0; i < 2; i++)
        #pragma unroll
        for (int j = 0; j < 6; j++)
            #pragma unroll
            for (int l = 0; l < 4; l++) acc[i][j][l] = 0.f;

    auto issue = [&](int c) {
        const int buf = c % STG;
        const uint32_t aS = s0 + buf*ASTAGE;
        const uint32_t bS = s0 + STG*ASTAGE + buf*BSTAGE;
        const int ac = c << 5;
        {
            const int row = t >> 2, seg = t & 3;
            if (EPI == 3) {
                const int kp = ac + seg*8;
                const int kk = kp >> 6, ci0 = kp & 63;
                const int kh = kk / 3, kw = kk - kh*3;
                const int ih = mh + kh - 1, iw = mw + kw - 1;
                const bool ok = ((unsigned)ih < HDIM) && ((unsigned)iw < WDIM);
                const int ihc = ok ? ih : 0, iwc = ok ? iw : 0;
                const __half* src = A + (((size_t)(mb*HDIM + ihc)*WDIM + iwc) << 6) + ci0;
                CPA16Z(aS + row*AROWB + seg*16, src, ok ? 16 : 0);
            } else {
                CPA16(aS + row*AROWB + seg*16,
                      A + (size_t)(m0 + row)*K + ac + seg*8);
            }
        }
        {
            const int row = t >> 2, seg = t & 3;
            CPA16(bS + row*BROWB + seg*16,
                  B + (size_t)(n0 + row)*K + ac + seg*8);
            if (t < 256) {
                const int idx = t + 512, row2 = idx >> 2, seg2 = idx & 3;
                CPA16(bS + row2*BROWB + seg2*16,
                      B + (size_t)(n0 + row2)*K + ac + seg2*8);
            }
        }
    };

    #pragma unroll
    for (int p = 0; p < 3; p++) {
        if (p < kc) issue(p);
        CPCOMMIT();
    }
    for (int c = 0; c < kc; c++) {
        CPWAIT(2);
        __syncthreads();
        if (c + 3 < kc) issue(c + 3);
        CPCOMMIT();
        const int buf = c % STG;
        const uint32_t aB = s0 + buf*ASTAGE;
        const uint32_t bB = s0 + STG*ASTAGE + buf*BSTAGE;
        #pragma unroll
        for (int ks = 0; ks < 2; ks++) {
            const int kb = ks * 32;
            uint32_t afr[2][4];
            #pragma unroll
            for (int am = 0; am < 2; am++)
                LDMX4(afr[am], aB + (uint32_t)((wm + am*16 + (lane & 15))*AROWB)
                             + kb + ((lane >> 4) << 4));
            uint32_t bf[3][4];
            #pragma unroll
            for (int bn = 0; bn < 3; bn++)
                LDMX4(bf[bn], bB + (uint32_t)((wn + bn*16 + ((mat & 2) << 2) + rr)*BROWB)
                            + kb + ((mat & 1) << 4));
            #pragma unroll
            for (int am = 0; am < 2; am++)
                #pragma unroll
                for (int bn = 0; bn < 3; bn++) {
                    MMA16816(acc[am][bn*2],   afr[am], bf[bn][0], bf[bn][1]);
                    MMA16816(acc[am][bn*2+1], afr[am], bf[bn][2], bf[bn][3]);
                }
        }
    }
    __syncthreads();

    // ---- epilogue pass 1 ----
    float lsum[2][2], lsq[2][2];
    #pragma unroll
    for (int am = 0; am < 2; am++)
        #pragma unroll
        for (int h = 0; h < 2; h++) { lsum[am][h] = 0.f; lsq[am][h] = 0.f; }
    #pragma unroll
    for (int am = 0; am < 2; am++) {
        #pragma unroll
        for (int nf = 0; nf < 6; nf++) {
            const int nn = n0 + wn + nf*8 + ((lane & 3) << 1);
            const float b0 = bias[nn], b1 = bias[nn + 1];
            #pragma unroll
            for (int h = 0; h < 2; h++) {
                const int m = m0 + wm + am*16 + (lane >> 2) + h*8;
                float o0 = acc[am][nf][h*2]     + b0;
                float o1 = acc[am][nf][h*2 + 1] + b1;
                if (EPI == 4 || EPI == 6) {
                    float2 rv = __half22float2(*(const __half2*)(resh + (size_t)m*N + nn));
                    o0 += rv.x; o1 += rv.y;
                }
                if (EPI == 6) {
                    float2 rv = __half22float2(*(const __half2*)(res2h + (size_t)m*N + nn));
                    o0 += rv.x; o1 += rv.y;
                }
                acc[am][nf][h*2]     = o0;
                acc[am][nf][h*2 + 1] = o1;
                if (EPI == 3 || EPI == 4) {
                    lsum[am][h] += o0 + o1;
                    lsq[am][h]  += o0*o0 + o1*o1;
                }
            }
        }
    }

    float mu[2][2], rs[2][2];
    if (EPI == 3 || EPI == 4) {
        float2* red = (float2*)dsm;
        #pragma unroll
        for (int am = 0; am < 2; am++)
            #pragma unroll
            for (int h = 0; h < 2; h++) {
                #pragma unroll
                for (int ox = 1; ox < 4; ox <<= 1) {
                    lsum[am][h] += __shfl_xor_sync(0xffffffffu, lsum[am][h], ox);
                    lsq[am][h]  += __shfl_xor_sync(0xffffffffu, lsq[am][h], ox);
                }
            }
        if ((lane & 3) == 0) {
            #pragma unroll
            for (int am = 0; am < 2; am++)
                #pragma unroll
                for (int h = 0; h < 2; h++) {
                    int row = wm + am*16 + (lane >> 2) + h*8;
                    red[row*4 + (wid & 3)] = make_float2(lsum[am][h], lsq[am][h]);
                }
        }
        __syncthreads();
        #pragma unroll
        for (int am = 0; am < 2; am++)
            #pragma unroll
            for (int h = 0; h < 2; h++) {
                int row = wm + am*16 + (lane >> 2) + h*8;
                float s = 0.f, q = 0.f;
                #pragma unroll
                for (int w = 0; w < 4; w++) {
                    float2 v = red[row*4 + w];
                    s += v.x; q += v.y;
                }
                float m_ = s * (1.f/192.f);
                float var = q * (1.f/192.f) - m_*m_;
                mu[am][h] = m_;
                rs[am][h] = rsqrtf(var + 1e-5f);
            }
    }

    // ---- epilogue pass 2 ----
    #pragma unroll
    for (int am = 0; am < 2; am++) {
        #pragma unroll
        for (int nf = 0; nf < 6; nf++) {
            const int nn = n0 + wn + nf*8 + ((lane & 3) << 1);
            #pragma unroll
            for (int h = 0; h < 2; h++) {
                const int m = m0 + wm + am*16 + (lane >> 2) + h*8;
                const float o0 = acc[am][nf][h*2], o1 = acc[am][nf][h*2 + 1];
                if (EPI == 6) {
                    const int bb = m / L, hw = m - bb*L;
                    Cf[((size_t)bb*CDIM + nn)*L + hw]     = o0;
                    Cf[((size_t)bb*CDIM + nn + 1)*L + hw] = o1;
                } else {
                    *(__half2*)(Ch + (size_t)m*N + nn) =
                        __halves2half2(__float2half_rn(o0), __float2half_rn(o1));
                    float y0 = (o0 - mu[am][h])*rs[am][h]*lnw[nn]     + lnb[nn];
                    float y1 = (o1 - mu[am][h])*rs[am][h]*lnw[nn + 1] + lnb[nn + 1];
                    *(__half2*)(Cs + (size_t)m*N + nn) =
                        __halves2half2(__float2half_rn(y0), __float2half_rn(y1));
                }
            }
        }
    }
}

// ---------------- A-resident GEMM for K=192, multiple 192-col blocks per CTA ------
// A panel (128x192 fp16) loaded once into smem (400B rows); B streamed (4 stages).
// EPI: 0 bias->Cs | 2 bias+GELU->Cs.
#define ARROW  400
#define SM_AR_A  (128*ARROW)                 // 51200
#define SMEM_AR  (SM_AR_A + STG*BSTAGE)      // 112640
template<int EPI, int NBLK>
__global__ __launch_bounds__(512) void mma_gemm_ar(
    const __half* __restrict__ A, const __half* __restrict__ B,
    const float* __restrict__ bias, __half* __restrict__ Cs, int N)
{
    extern __shared__ __align__(16) char dsm[];
    const uint32_t s0 = smem_u32(dsm);
    const uint32_t aR = s0, bR = s0 + SM_AR_A;
    const int t = threadIdx.x, wid = t >> 5, lane = t & 31;
    const int m0 = blockIdx.x * 128;
    const int wm = (wid >> 2) * 32, wn = (wid & 3) * 48;
    const int mat = lane >> 3, rr = lane & 7;

    // A panel load: 128 rows x 24 segs of 16B = 3072, 6 per thread
    #pragma unroll
    for (int i = 0; i < 6; i++) {
        const int idx = t + i*512, row = idx / 24, seg = idx % 24;
        CPA16(aR + row*ARROW + seg*16, A + (size_t)(m0 + row)*192 + seg*8);
    }

    auto issueB = [&](int g) {
        const int nb = g / 6, c = g - nb*6;
        const int n0g = nb*192, ac = c << 5;
        const uint32_t bS = bR + (g & 3)*BSTAGE;
        const int row = t >> 2, seg = t & 3;
        CPA16(bS + row*BROWB + seg*16,
              B + (size_t)(n0g + row)*192 + ac + seg*8);
        if (t < 256) {
            const int idx = t + 512, row2 = idx >> 2, seg2 = idx & 3;
            CPA16(bS + row2*BROWB + seg2*16,
                  B + (size_t)(n0g + row2)*192 + ac + seg2*8);
        }
    };

    issueB(0); CPCOMMIT();   // group 0 carries the A panel too
    issueB(1); CPCOMMIT();
    issueB(2); CPCOMMIT();

    for (int nb = 0; nb < NBLK; nb++) {
        float acc[2][6][4];
        #pragma unroll
        for (int i = 0; i < 2; i++)
            #pragma unroll
            for (int j = 0; j < 6; j++)
                #pragma unroll
                for (int l = 0; l < 4; l++) acc[i][j][l] = 0.f;

        for (int c = 0; c < 6; c++) {
            const int g = nb*6 + c;
            CPWAIT(2);
            __syncthreads();
            if (g + 3 < NBLK*6) issueB(g + 3);
            CPCOMMIT();
            const uint32_t bB = bR + (g & 3)*BSTAGE;
            #pragma unroll
            for (int ks = 0; ks < 2; ks++) {
                const int kbA = c*64 + ks*32;   // byte offset within A row
                const int kbB = ks*32;
                uint32_t afr[2][4];
                #pragma unroll
                for (int am = 0; am < 2; am++)
                    LDMX4(afr[am], aR + (uint32_t)((wm + am*16 + (lane & 15))*ARROW)
                                 + kbA + ((lane >> 4) << 4));
                uint32_t bf[3][4];
                #pragma unroll
                for (int bn = 0; bn < 3; bn++)
                    LDMX4(bf[bn], bB + (uint32_t)((wn + bn*16 + ((mat & 2) << 2) + rr)*BROWB)
                                + kbB + ((mat & 1) << 4));
                #pragma unroll
                for (int am = 0; am < 2; am++)
                    #pragma unroll
                    for (int bn = 0; bn < 3; bn++) {
                        MMA16816(acc[am][bn*2],   afr[am], bf[bn][0], bf[bn][1]);
                        MMA16816(acc[am][bn*2+1], afr[am], bf[bn][2], bf[bn][3]);
                    }
            }
        }

        // epilogue for this column block
        const int n0 = nb*192;
        #pragma unroll
        for (int am = 0; am < 2; am++) {
            #pragma unroll
            for (int nf = 0; nf < 6; nf++) {
                const int nn = n0 + wn + nf*8 + ((lane & 3) << 1);
                const float b0 = bias[nn], b1 = bias[nn + 1];
                #pragma unroll
                for (int h = 0; h < 2; h++) {
                    const int m = m0 + wm + am*16 + (lane >> 2) + h*8;
                    float o0 = acc[am][nf][h*2]     + b0;
                    float o1 = acc[am][nf][h*2 + 1] + b1;
                    if (EPI == 2) {
                        o0 = 0.5f*o0*(1.0f + erff(o0*0.70710678118654752f));
                        o1 = 0.5f*o1*(1.0f + erff(o1*0.70710678118654752f));
                    }
                    *(__half2*)(Cs + (size_t)m*N + nn) =
                        __halves2half2(__float2half_rn(o0), __float2half_rn(o1));
                }
            }
        }
    }
}

// ---------------- fused prep: NHWC convert + weight converts + rel-pos bias -------
#define NB_X  896
#define W_C1 (CDIM*KCONV)
#define W_C2 (W_C1 + 3*CDIM*CDIM)
#define W_C3 (W_C2 + CDIM*CDIM)
#define W_C4 (W_C3 + 4*CDIM*CDIM)
#define W_C5 (W_C4 + CDIM*4*CDIM)
#define NB_W 2160
#define NB_B 84
__global__ void prep_all(const float* __restrict__ x, __half* __restrict__ xh,
                         const float* __restrict__ w0, __half* __restrict__ d0,
                         const float* __restrict__ w1, __half* __restrict__ d1,
                         const float* __restrict__ w2, __half* __restrict__ d2,
                         const float* __restrict__ w3, __half* __restrict__ d3,
                         const float* __restrict__ w4, __half* __restrict__ d4,
                         const float* __restrict__ tab, const int* __restrict__ idx,
                         float* __restrict__ biasout)
{
    const int bid = blockIdx.x;
    if (bid < NB_X) {
        __shared__ float tile[CIN][WDIM + 1];
        const int b = bid / HDIM, h = bid - b*HDIM;
        for (int i = threadIdx.x; i < CIN*WDIM; i += 256) {
            int c = i / WDIM, w = i - c*WDIM;
            tile[c][w] = x[((size_t)(b*CIN + c)*HDIM + h)*WDIM + w];
        }
        __syncthreads();
        for (int i = threadIdx.x; i < WDIM*8; i += 256) {
            int w = i >> 3, cs = (i & 7)*8;
            __half v[8];
            #pragma unroll
            for (int u = 0; u < 8; u++) v[u] = __float2half_rn(tile[cs + u][w]);
            *(uint4*)(xh + (((size_t)(b*HDIM + h)*WDIM + w) << 6) + cs) = *(uint4*)v;
        }
    } else if (bid < NB_X + NB_W) {
        int i = (bid - NB_X)*256 + threadIdx.x;
        if (i < W_C1) {
            int n = i / KCONV, k = i - n*KCONV;
            int ci = k / 9, r = k - ci*9;
            d0[n*KCONV + r*64 + ci] = __float2half_rn(w0[i]);
        } else if (i < W_C5) {
            const float* s; __half* d; int off;
            if      (i < W_C2) { s = w1; d = d1; off = W_C1; }
            else if (i < W_C3) { s = w2; d = d2; off = W_C2; }
            else if (i < W_C4) { s = w3; d = d3; off = W_C3; }
            else               { s = w4; d = d4; off = W_C4; }
            d[i - off] = __float2half_rn(s[i - off]);
        }
    } else {
        int i = (bid - NB_X - NB_W)*256 + threadIdx.x;
        if (i < NH*64*56) {
            int h = i / (64*56), rem = i % (64*56);
            int r = rem / 56, c = rem % 56;
            float v;
            if (c >= NWIN)      v = -1e30f;
            else if (r >= NWIN) v = 0.f;
            else                v = tab[idx[r*NWIN + c]*NH + h];
            biasout[i] = v;
        }
    }
}

// ---------------- HMMA window attention (cp.async loads) ----------------
#define QROW 200
#define SM_QS  256
#define SM_KS  (SM_QS + 64*400)
#define SM_VS  (SM_KS + 64*400)
#define SMEM_ATT (SM_VS + 64*400)   // 77056
__global__ __launch_bounds__(384, 2) void attn_mma(const __half* __restrict__ qkv,
                                                   const float* __restrict__ biasp,
                                                   __half* __restrict__ o)
{
    extern __shared__ __align__(16) char sm[];
    int* toks = (int*)sm;
    __half* QS = (__half*)(sm + SM_QS);
    __half* KS = (__half*)(sm + SM_KS);
    __half* VS = (__half*)(sm + SM_VS);
    const int t = threadIdx.x, wid = t >> 5, lane = t & 31;
    const int wi = blockIdx.x;
    const int b = wi >> 8, r_ = wi & 255, wh = r_ >> 4, ww = r_ & 15;
    if (t < NWIN) toks[t] = b*L + (wh*WS + t/WS)*WDIM + (ww*WS + t%WS);
    __syncthreads();

    const uint32_t qsB = smem_u32(QS), ksB = smem_u32(KS), vsB = smem_u32(VS);

    for (int idx = t; idx < NWIN*24; idx += 384) {
        int p = idx / 24, seg = idx % 24;
        const __half* src = qkv + (size_t)toks[p]*576 + seg*8;
        CPA16(qsB + p*400 + seg*16, src);
        CPA16(ksB + p*400 + seg*16, src + 192);
        CPA16(vsB + p*400 + seg*16, src + 384);
    }
    for (int idx = t; idx < 15*24; idx += 384) {
        int rr2 = idx / 24, seg = idx % 24;
        uint4 z = make_uint4(0,0,0,0);
        *(uint4*)(QS + (NWIN + rr2)*QROW + seg*8) = z;
        *(uint4*)(KS + (NWIN + rr2)*QROW + seg*8) = z;
        *(uint4*)(VS + (NWIN + rr2)*QROW + seg*8) = z;
    }
    CPCOMMIT();
    CPWAIT(0);
    __syncthreads();

    const int h = wid >> 1, m0 = (wid & 1)*32;
    const int mat = lane >> 3, rr = lane & 7;

    float accS[2][7][4];
    #pragma unroll
    for (int i = 0; i < 2; i++)
        #pragma unroll
        for (int j = 0; j < 7; j++)
            #pragma unroll
            for (int l = 0; l < 4; l++) accS[i][j][l] = 0.f;
    #pragma unroll
    for (int ks = 0; ks < 2; ks++) {
        const int kb = ks*32;
        uint32_t af[2][4];
        #pragma unroll
        for (int mf = 0; mf < 2; mf++)
            LDMX4(af[mf], qsB + (uint32_t)((m0 + mf*16 + (lane & 15))*400)
                        + h*64 + kb + ((lane >> 4) << 4));
        uint32_t bf[4][4];
        #pragma unroll
        for (int bn = 0; bn < 4; bn++)
            LDMX4(bf[bn], ksB + (uint32_t)((bn*16 + ((mat & 2) << 2) + rr)*400)
                        + h*64 + kb + ((mat & 1) << 4));
        #pragma unroll
        for (int mf = 0; mf < 2; mf++)
            #pragma unroll
            for (int nf = 0; nf < 7; nf++)
                MMA16816(accS[mf][nf], af[mf], bf[nf >> 1][(nf & 1)*2], bf[nf >> 1][(nf & 1)*2 + 1]);
    }

    const float scale = 0.17677669529663687f;
    #pragma unroll
    for (int mf = 0; mf < 2; mf++) {
        const int rl = m0 + mf*16 + (lane >> 2);
        const float* b0 = biasp + (h*64 + rl)*56;
        const float* b1 = biasp + (h*64 + rl + 8)*56;
        #pragma unroll
        for (int nf = 0; nf < 7; nf++) {
            const int c0 = nf*8 + (lane & 3)*2;
            float2 blo = *(const float2*)(b0 + c0);
            float2 bhi = *(const float2*)(b1 + c0);
            accS[mf][nf][0] = accS[mf][nf][0]*scale + blo.x;
            accS[mf][nf][1] = accS[mf][nf][1]*scale + blo.y;
            accS[mf][nf][2] = accS[mf][nf][2]*scale + bhi.x;
            accS[mf][nf][3] = accS[mf][nf][3]*scale + bhi.y;
        }
        float mlo = -1e30f, mhi = -1e30f;
        #pragma unroll
        for (int nf = 0; nf < 7; nf++) {
            mlo = fmaxf(mlo, fmaxf(accS[mf][nf][0], accS[mf][nf][1]));
            mhi = fmaxf(mhi, fmaxf(accS[mf][nf][2], accS[mf][nf][3]));
        }
        #pragma unroll
        for (int ox = 1; ox < 4; ox <<= 1) {
            mlo = fmaxf(mlo, __shfl_xor_sync(0xffffffffu, mlo, ox));
            mhi = fmaxf(mhi, __shfl_xor_sync(0xffffffffu, mhi, ox));
        }
        float slo = 0.f, shi = 0.f;
        #pragma unroll
        for (int nf = 0; nf < 7; nf++) {
            accS[mf][nf][0] = __expf(accS[mf][nf][0] - mlo);
            accS[mf][nf][1] = __expf(accS[mf][nf][1] - mlo);
            accS[mf][nf][2] = __expf(accS[mf][nf][2] - mhi);
            accS[mf][nf][3] = __expf(accS[mf][nf][3] - mhi);
            slo += accS[mf][nf][0] + accS[mf][nf][1];
            shi += accS[mf][nf][2] + accS[mf][nf][3];
        }
        #pragma unroll
        for (int ox = 1; ox < 4; ox <<= 1) {
            slo += __shfl_xor_sync(0xffffffffu, slo, ox);
            shi += __shfl_xor_sync(0xffffffffu, shi, ox);
        }
        const float ilo = 1.f/slo, ihi = 1.f/shi;
        #pragma unroll
        for (int nf = 0; nf < 7; nf++) {
            accS[mf][nf][0] *= ilo; accS[mf][nf][1] *= ilo;
            accS[mf][nf][2] *= ihi; accS[mf][nf][3] *= ihi;
        }
    }

    float accO[2][4][4];
    #pragma unroll
    for (int i = 0; i < 2; i++)
        #pragma unroll
        for (int j = 0; j < 4; j++)
            #pragma unroll
            for (int l = 0; l < 4; l++) accO[i][j][l] = 0.f;
    #pragma unroll
    for (int kt = 0; kt < 4; kt++) {
        uint32_t bf[2][4];
        #pragma unroll
        for (int bn = 0; bn < 2; bn++)
            LDMX4T(bf[bn], vsB + (uint32_t)((kt*16 + ((mat & 1) << 3) + rr)*400)
                         + h*64 + bn*32 + ((mat & 2) << 3));
        #pragma unroll
        for (int mf = 0; mf < 2; mf++) {
            const int nf0 = 2*kt, nf1 = 2*kt + 1;
            uint32_t a0 = packh2(accS[mf][nf0][0], accS[mf][nf0][1]);
            uint32_t a1 = packh2(accS[mf][nf0][2], accS[mf][nf0][3]);
            uint32_t a2 = 0, a3 = 0;
            if (nf1 < 7) {
                a2 = packh2(accS[mf][nf1][0], accS[mf][nf1][1]);
                a3 = packh2(accS[mf][nf1][2], accS[mf][nf1][3]);
            }
            #pragma unroll
            for (int nf = 0; nf < 4; nf++)
                MMA16816R(accO[mf][nf], a0, a1, a2, a3,
                          bf[nf >> 1][(nf & 1)*2], bf[nf >> 1][(nf & 1)*2 + 1]);
        }
    }

    #pragma unroll
    for (int mf = 0; mf < 2; mf++) {
        const int rl = m0 + mf*16 + (lane >> 2);
        #pragma unroll
        for (int nf = 0; nf < 4; nf++) {
            const int c = nf*8 + (lane & 3)*2;
            if (rl < NWIN)
                *(__half2*)(o + (size_t)toks[rl]*CDIM + h*HD + c) =
                    __halves2half2(__float2half_rn(accO[mf][nf][0]),
                                   __float2half_rn(accO[mf][nf][1]));
            if (rl + 8 < NWIN)
                *(__half2*)(o + (size_t)toks[rl + 8]*CDIM + h*HD + c) =
                    __halves2half2(__float2half_rn(accO[mf][nf][2]),
                                   __float2half_rn(accO[mf][nf][3]));
        }
    }
}

// ---------------- launch ----------------
extern "C" void kernel_launch(void* const* d_in, const int* in_sizes, int n_in,
                              void* d_out, int out_size)
{
    const float* x        = (const float*)d_in[0];
    const float* proj_w   = (const float*)d_in[1];
    const float* proj_b   = (const float*)d_in[2];
    const float* ln1_w    = (const float*)d_in[3];
    const float* ln1_b    = (const float*)d_in[4];
    const float* qkv_w    = (const float*)d_in[5];
    const float* qkv_b    = (const float*)d_in[6];
    const float* rel_tab  = (const float*)d_in[7];
    const float* apw      = (const float*)d_in[8];
    const float* apb      = (const float*)d_in[9];
    const float* ln2_w    = (const float*)d_in[10];
    const float* ln2_b    = (const float*)d_in[11];
    const float* fc1_w    = (const float*)d_in[12];
    const float* fc1_b    = (const float*)d_in[13];
    const float* fc2_w    = (const float*)d_in[14];
    const float* fc2_b    = (const float*)d_in[15];
    const int*   rel_idx  = (const int*)d_in[16];
    float* out = (float*)d_out;

    __half *xhp, *lnq, *aoh, *m1h, *qkvh, *xth, *t1h, *wconv, *wqkv, *wap, *wfc1, *wfc2;
    float *biasp;
    cudaGetSymbolAddress((void**)&xhp,   g_xh);
    cudaGetSymbolAddress((void**)&lnq,   g_ln);
    cudaGetSymbolAddress((void**)&aoh,   g_ao);
    cudaGetSymbolAddress((void**)&m1h,   g_m1);
    cudaGetSymbolAddress((void**)&qkvh,  g_qkv);
    cudaGetSymbolAddress((void**)&xth,   g_xt);
    cudaGetSymbolAddress((void**)&t1h,   g_t1);
    cudaGetSymbolAddress((void**)&biasp, g_bias);
    cudaGetSymbolAddress((void**)&wconv, g_wconv);
    cudaGetSymbolAddress((void**)&wqkv,  g_wqkv);
    cudaGetSymbolAddress((void**)&wap,   g_wap);
    cudaGetSymbolAddress((void**)&wfc1,  g_wfc1);
    cudaGetSymbolAddress((void**)&wfc2,  g_wfc2);

    cudaFuncSetAttribute(mma_gemm<3>, cudaFuncAttributeMaxDynamicSharedMemorySize, SMEM_GEMM);
    cudaFuncSetAttribute(mma_gemm<4>, cudaFuncAttributeMaxDynamicSharedMemorySize, SMEM_GEMM);
    cudaFuncSetAttribute(mma_gemm<6>, cudaFuncAttributeMaxDynamicSharedMemorySize, SMEM_GEMM);
    cudaFuncSetAttribute(mma_gemm_ar<0,3>, cudaFuncAttributeMaxDynamicSharedMemorySize, SMEM_AR);
    cudaFuncSetAttribute(mma_gemm_ar<2,4>, cudaFuncAttributeMaxDynamicSharedMemorySize, SMEM_AR);
    cudaFuncSetAttribute(attn_mma,    cudaFuncAttributeMaxDynamicSharedMemorySize, SMEM_ATT);

    const int MB = TKN/128;   // 784

    prep_all<<<NB_X + NB_W + NB_B, 256>>>(x, xhp,
                                          proj_w, wconv, qkv_w, wqkv, apw, wap,
                                          fc1_w, wfc1, fc2_w, wfc2,
                                          rel_tab, rel_idx, biasp);
    // conv (implicit, A = xh NHWC) + fused LN1: xt (fp16) + lnq
    mma_gemm<3><<<dim3(1, MB), 512, SMEM_GEMM>>>(xhp, wconv, proj_b, nullptr, nullptr,
                                                 ln1_w, ln1_b, nullptr, xth, lnq, CDIM, KCONV);
    // qkv: A-resident, 3 column blocks per CTA
    mma_gemm_ar<0,3><<<MB, 512, SMEM_AR>>>(lnq, wqkv, qkv_b, qkvh, 3*CDIM);
    attn_mma<<<NWTOT, 384, SMEM_ATT>>>(qkvh, biasp, aoh);
    // attn-proj + residual(xt) + LN2
    mma_gemm<4><<<dim3(1, MB), 512, SMEM_GEMM>>>(aoh, wap, apb, xth, nullptr,
                                                 ln2_w, ln2_b, nullptr, t1h, lnq, CDIM, CDIM);
    // fc1 + GELU: A-resident, 4 column blocks per CTA
    mma_gemm_ar<2,4><<<MB, 512, SMEM_AR>>>(lnq, wfc1, fc1_b, m1h, 4*CDIM);
    // fc2 + residual(t1) + shortcut(xt) -> NCHW out
    mma_gemm<6><<<dim3(1, MB), 512, SMEM_GEMM>>>(m1h, wfc2, fc2_b, t1h, xth,
                                                 nullptr, nullptr, out, nullptr, nullptr, CDIM, 4*CDIM);
}

// round 17
// speedup vs baseline: 1.0484x; 1.0484x over previous
#include <cuda_runtime.h>
#include <cuda_fp16.h>
#include <math.h>
#include <stdint.h>

// ---------------- problem constants ----------------
#define BATCH   8
#define CIN     64
#define CDIM    192
#define HDIM    112
#define WDIM    112
#define L       (HDIM*WDIM)          // 12544
#define TKN     (BATCH*L)            // 100352
#define WS      7
#define NWIN    49
#define NH      6
#define HD      32
#define NWTOT   2048
#define KCONV   576

typedef unsigned long long u64;

__device__ __forceinline__ uint32_t smem_u32(const void* p) {
    uint32_t a;
    asm("{ .reg .u64 t; cvta.to.shared.u64 t, %1; cvt.u32.u64 %0, t; }" : "=r"(a) : "l"(p));
    return a;
}
__device__ __forceinline__ uint32_t packh2(float x, float y) {
    __half2 h = __floats2half2_rn(x, y);
    return *(uint32_t*)&h;
}

// ---------------- warp-MMA + cp.async primitives (base ISA) ----------------
#define LDMX4(r, addr) \
    asm volatile("ldmatrix.sync.aligned.m8n8.x4.shared.b16 {%0,%1,%2,%3}, [%4];" \
        : "=r"((r)[0]), "=r"((r)[1]), "=r"((r)[2]), "=r"((r)[3]) : "r"(addr))

#define LDMX4T(r, addr) \
    asm volatile("ldmatrix.sync.aligned.m8n8.x4.trans.shared.b16 {%0,%1,%2,%3}, [%4];" \
        : "=r"((r)[0]), "=r"((r)[1]), "=r"((r)[2]), "=r"((r)[3]) : "r"(addr))

#define MMA16816(c, a, b0, b1) \
    asm volatile("mma.sync.aligned.m16n8k16.row.col.f32.f16.f16.f32 " \
        "{%0,%1,%2,%3}, {%4,%5,%6,%7}, {%8,%9}, {%0,%1,%2,%3};" \
        : "+f"((c)[0]), "+f"((c)[1]), "+f"((c)[2]), "+f"((c)[3]) \
        : "r"((a)[0]), "r"((a)[1]), "r"((a)[2]), "r"((a)[3]), "r"(b0), "r"(b1))

#define MMA16816R(c, a0, a1, a2, a3, b0, b1) \
    asm volatile("mma.sync.aligned.m16n8k16.row.col.f32.f16.f16.f32 " \
        "{%0,%1,%2,%3}, {%4,%5,%6,%7}, {%8,%9}, {%0,%1,%2,%3};" \
        : "+f"((c)[0]), "+f"((c)[1]), "+f"((c)[2]), "+f"((c)[3]) \
        : "r"(a0), "r"(a1), "r"(a2), "r"(a3), "r"(b0), "r"(b1))

#define CPA16(dst, src) \
    asm volatile("cp.async.ca.shared.global [%0], [%1], 16;" :: "r"(dst), "l"(src))
#define CPA16Z(dst, src, sz) \
    asm volatile("cp.async.ca.shared.global [%0], [%1], 16, %2;" :: "r"(dst), "l"(src), "r"(sz))
#define CPCOMMIT() asm volatile("cp.async.commit_group;" ::: "memory")
#define CPWAIT(n)  asm volatile("cp.async.wait_group %0;" :: "n"(n) : "memory")

// ---------------- scratch (static device) ----------------
__device__ __half g_xh [(size_t)TKN*CIN];       // x in NHWC fp16
__device__ __half g_ao [(size_t)TKN*CDIM];
__device__ __half g_m1 [(size_t)TKN*4*CDIM];
__device__ __half g_qkv[(size_t)TKN*3*CDIM];
__device__ __half g_xt [(size_t)TKN*CDIM];
__device__ __half g_t1 [(size_t)TKN*CDIM];
__device__ float g_bias[NH*64*56];
__device__ __half g_wconv[CDIM*KCONV];          // remapped: k' = (kh*3+kw)*64 + ci
__device__ __half g_wqkv [3*CDIM*CDIM];
__device__ __half g_wap  [CDIM*CDIM];
__device__ __half g_wfc1 [4*CDIM*CDIM];
__device__ __half g_wfc2 [CDIM*4*CDIM];

#define AROWB  80
#define BROWB  80
#define ASTAGE 10240
#define BSTAGE 15360
#define STG    4
#define SMEM_GEMM (STG*(ASTAGE+BSTAGE))      // 102400
#define ARROW  400
#define SM_AR_A  (128*ARROW)                 // 51200
#define SMEM_FUSE (SM_AR_A + STG*BSTAGE)     // 112640 (covers phase-1's 102400 too)

// ---------------- FUSED: [conv|proj] GEMM + LN -> smem A -> consumer GEMM --------
// PH1: 3 = implicit conv (A=xh NHWC, K=576), 4 = proj + residual (A gmem, K=192)
// Phase 1 writes Ch (fp16 residual stream) + LN result into smem A region.
// Phase 2: NBLK x 192 column blocks of consumer GEMM (B streamed), EPI2: 0 bias, 2 bias+GELU.
template<int PH1, int NBLK, int EPI2>
__global__ __launch_bounds__(512) void fused_gemm(
    const __half* __restrict__ A, const __half* __restrict__ B1,
    const float* __restrict__ bias1, const __half* __restrict__ resh,
    const float* __restrict__ lnw, const float* __restrict__ lnb,
    __half* __restrict__ Ch,
    const __half* __restrict__ B2, const float* __restrict__ bias2,
    __half* __restrict__ C2, int K1)
{
    extern __shared__ __align__(16) char dsm[];
    const uint32_t s0 = smem_u32(dsm);
    const int t = threadIdx.x, wid = t >> 5, lane = t & 31;
    const int m0 = blockIdx.x * 128;
    const int wm = (wid >> 2) * 32, wn = (wid & 3) * 48;
    const int mat = lane >> 3, rr = lane & 7;
    const int kc = K1 >> 5;

    int mb = 0, mh = 0, mw = 0;
    if (PH1 == 3) {
        const int m = m0 + (t >> 2);
        mb = m / L;
        const int hw = m - mb*L;
        mh = hw / WDIM;
        mw = hw - mh*WDIM;
    }

    float acc[2][6][4];
    #pragma unroll
    for (int i = 0; i < 2; i++)
        #pragma unroll
        for (int j = 0; j < 6; j++)
            #pragma unroll
            for (int l = 0; l < 4; l++) acc[i][j][l] = 0.f;

    auto issue = [&](int c) {
        const int buf = c % STG;
        const uint32_t aS = s0 + buf*ASTAGE;
        const uint32_t bS = s0 + STG*ASTAGE + buf*BSTAGE;
        const int ac = c << 5;
        {
            const int row = t >> 2, seg = t & 3;
            if (PH1 == 3) {
                const int kp = ac + seg*8;
                const int kk = kp >> 6, ci0 = kp & 63;
                const int kh = kk / 3, kw = kk - kh*3;
                const int ih = mh + kh - 1, iw = mw + kw - 1;
                const bool ok = ((unsigned)ih < HDIM) && ((unsigned)iw < WDIM);
                const int ihc = ok ? ih : 0, iwc = ok ? iw : 0;
                const __half* src = A + (((size_t)(mb*HDIM + ihc)*WDIM + iwc) << 6) + ci0;
                CPA16Z(aS + row*AROWB + seg*16, src, ok ? 16 : 0);
            } else {
                CPA16(aS + row*AROWB + seg*16,
                      A + (size_t)(m0 + row)*K1 + ac + seg*8);
            }
        }
        {
            const int row = t >> 2, seg = t & 3;
            CPA16(bS + row*BROWB + seg*16,
                  B1 + (size_t)(row)*K1 + ac + seg*8);
            if (t < 256) {
                const int idx = t + 512, row2 = idx >> 2, seg2 = idx & 3;
                CPA16(bS + row2*BROWB + seg2*16,
                      B1 + (size_t)(row2)*K1 + ac + seg2*8);
            }
        }
    };

    #pragma unroll
    for (int p = 0; p < 3; p++) {
        if (p < kc) issue(p);
        CPCOMMIT();
    }
    for (int c = 0; c < kc; c++) {
        CPWAIT(2);
        __syncthreads();
        if (c + 3 < kc) issue(c + 3);
        CPCOMMIT();
        const int buf = c % STG;
        const uint32_t aB = s0 + buf*ASTAGE;
        const uint32_t bB = s0 + STG*ASTAGE + buf*BSTAGE;
        #pragma unroll
        for (int ks = 0; ks < 2; ks++) {
            const int kb = ks * 32;
            uint32_t afr[2][4];
            #pragma unroll
            for (int am = 0; am < 2; am++)
                LDMX4(afr[am], aB + (uint32_t)((wm + am*16 + (lane & 15))*AROWB)
                             + kb + ((lane >> 4) << 4));
            uint32_t bf[3][4];
            #pragma unroll
            for (int bn = 0; bn < 3; bn++)
                LDMX4(bf[bn], bB + (uint32_t)((wn + bn*16 + ((mat & 2) << 2) + rr)*BROWB)
                            + kb + ((mat & 1) << 4));
            #pragma unroll
            for (int am = 0; am < 2; am++)
                #pragma unroll
                for (int bn = 0; bn < 3; bn++) {
                    MMA16816(acc[am][bn*2],   afr[am], bf[bn][0], bf[bn][1]);
                    MMA16816(acc[am][bn*2+1], afr[am], bf[bn][2], bf[bn][3]);
                }
        }
    }
    CPWAIT(0);
    __syncthreads();

    // ---- phase-1 epilogue: bias (+res), LN stats ----
    float lsum[2][2], lsq[2][2];
    #pragma unroll
    for (int am = 0; am < 2; am++)
        #pragma unroll
        for (int h = 0; h < 2; h++) { lsum[am][h] = 0.f; lsq[am][h] = 0.f; }
    #pragma unroll
    for (int am = 0; am < 2; am++) {
        #pragma unroll
        for (int nf = 0; nf < 6; nf++) {
            const int nn = wn + nf*8 + ((lane & 3) << 1);
            const float b0 = bias1[nn], b1 = bias1[nn + 1];
            #pragma unroll
            for (int h = 0; h < 2; h++) {
                const int m = m0 + wm + am*16 + (lane >> 2) + h*8;
                float o0 = acc[am][nf][h*2]     + b0;
                float o1 = acc[am][nf][h*2 + 1] + b1;
                if (PH1 == 4) {
                    float2 rv = __half22float2(*(const __half2*)(resh + (size_t)m*CDIM + nn));
                    o0 += rv.x; o1 += rv.y;
                }
                acc[am][nf][h*2]     = o0;
                acc[am][nf][h*2 + 1] = o1;
                lsum[am][h] += o0 + o1;
                lsq[am][h]  += o0*o0 + o1*o1;
            }
        }
    }

    float mu[2][2], rs[2][2];
    {
        float2* red = (float2*)dsm;
        #pragma unroll
        for (int am = 0; am < 2; am++)
            #pragma unroll
            for (int h = 0; h < 2; h++) {
                #pragma unroll
                for (int ox = 1; ox < 4; ox <<= 1) {
                    lsum[am][h] += __shfl_xor_sync(0xffffffffu, lsum[am][h], ox);
                    lsq[am][h]  += __shfl_xor_sync(0xffffffffu, lsq[am][h], ox);
                }
            }
        if ((lane & 3) == 0) {
            #pragma unroll
            for (int am = 0; am < 2; am++)
                #pragma unroll
                for (int h = 0; h < 2; h++) {
                    int row = wm + am*16 + (lane >> 2) + h*8;
                    red[row*4 + (wid & 3)] = make_float2(lsum[am][h], lsq[am][h]);
                }
        }
        __syncthreads();
        #pragma unroll
        for (int am = 0; am < 2; am++)
            #pragma unroll
            for (int h = 0; h < 2; h++) {
                int row = wm + am*16 + (lane >> 2) + h*8;
                float s = 0.f, q = 0.f;
                #pragma unroll
                for (int w = 0; w < 4; w++) {
                    float2 v = red[row*4 + w];
                    s += v.x; q += v.y;
                }
                float m_ = s * (1.f/192.f);
                float var = q * (1.f/192.f) - m_*m_;
                mu[am][h] = m_;
                rs[am][h] = rsqrtf(var + 1e-5f);
            }
    }
    __syncthreads();   // red reads done before A-region stores

    // ---- write residual stream to gmem + LN result to smem A region ----
    const uint32_t aR = s0;
    #pragma unroll
    for (int am = 0; am < 2; am++) {
        #pragma unroll
        for (int nf = 0; nf < 6; nf++) {
            const int nn = wn + nf*8 + ((lane & 3) << 1);
            #pragma unroll
            for (int h = 0; h < 2; h++) {
                const int rl = wm + am*16 + (lane >> 2) + h*8;
                const int m = m0 + rl;
                const float o0 = acc[am][nf][h*2], o1 = acc[am][nf][h*2 + 1];
                *(__half2*)(Ch + (size_t)m*CDIM + nn) =
                    __halves2half2(__float2half_rn(o0), __float2half_rn(o1));
                float y0 = (o0 - mu[am][h])*rs[am][h]*lnw[nn]     + lnb[nn];
                float y1 = (o1 - mu[am][h])*rs[am][h]*lnw[nn + 1] + lnb[nn + 1];
                *(__half2*)(dsm + rl*ARROW + nn*2) =
                    __halves2half2(__float2half_rn(y0), __float2half_rn(y1));
            }
        }
    }
    __syncthreads();

    // ---- phase 2: consumer GEMM, A resident in smem, B streamed ----
    const uint32_t bR = s0 + SM_AR_A;
    auto issueB = [&](int g) {
        const int nb = g / 6, c = g - nb*6;
        const int n0g = nb*192, ac = c << 5;
        const uint32_t bS = bR + (g & 3)*BSTAGE;
        const int row = t >> 2, seg = t & 3;
        CPA16(bS + row*BROWB + seg*16,
              B2 + (size_t)(n0g + row)*192 + ac + seg*8);
        if (t < 256) {
            const int idx = t + 512, row2 = idx >> 2, seg2 = idx & 3;
            CPA16(bS + row2*BROWB + seg2*16,
                  B2 + (size_t)(n0g + row2)*192 + ac + seg2*8);
        }
    };
    issueB(0); CPCOMMIT();
    issueB(1); CPCOMMIT();
    issueB(2); CPCOMMIT();

    const int N2 = NBLK*192;
    for (int nb = 0; nb < NBLK; nb++) {
        float ac2[2][6][4];
        #pragma unroll
        for (int i = 0; i < 2; i++)
            #pragma unroll
            for (int j = 0; j < 6; j++)
                #pragma unroll
                for (int l = 0; l < 4; l++) ac2[i][j][l] = 0.f;

        for (int c = 0; c < 6; c++) {
            const int g = nb*6 + c;
            CPWAIT(2);
            __syncthreads();
            if (g + 3 < NBLK*6) issueB(g + 3);
            CPCOMMIT();
            const uint32_t bB = bR + (g & 3)*BSTAGE;
            #pragma unroll
            for (int ks = 0; ks < 2; ks++) {
                const int kbA = c*64 + ks*32;
                const int kbB = ks*32;
                uint32_t afr[2][4];
                #pragma unroll
                for (int am = 0; am < 2; am++)
                    LDMX4(afr[am], aR + (uint32_t)((wm + am*16 + (lane & 15))*ARROW)
                                 + kbA + ((lane >> 4) << 4));
                uint32_t bf[3][4];
                #pragma unroll
                for (int bn = 0; bn < 3; bn++)
                    LDMX4(bf[bn], bB + (uint32_t)((wn + bn*16 + ((mat & 2) << 2) + rr)*BROWB)
                                + kbB + ((mat & 1) << 4));
                #pragma unroll
                for (int am = 0; am < 2; am++)
                    #pragma unroll
                    for (int bn = 0; bn < 3; bn++) {
                        MMA16816(ac2[am][bn*2],   afr[am], bf[bn][0], bf[bn][1]);
                        MMA16816(ac2[am][bn*2+1], afr[am], bf[bn][2], bf[bn][3]);
                    }
            }
        }
        const int n0 = nb*192;
        #pragma unroll
        for (int am = 0; am < 2; am++) {
            #pragma unroll
            for (int nf = 0; nf < 6; nf++) {
                const int nn = n0 + wn + nf*8 + ((lane & 3) << 1);
                const float b0 = bias2[nn], b1 = bias2[nn + 1];
                #pragma unroll
                for (int h = 0; h < 2; h++) {
                    const int m = m0 + wm + am*16 + (lane >> 2) + h*8;
                    float o0 = ac2[am][nf][h*2]     + b0;
                    float o1 = ac2[am][nf][h*2 + 1] + b1;
                    if (EPI2 == 2) {
                        o0 = 0.5f*o0*(1.0f + erff(o0*0.70710678118654752f));
                        o1 = 0.5f*o1*(1.0f + erff(o1*0.70710678118654752f));
                    }
                    *(__half2*)(C2 + (size_t)m*N2 + nn) =
                        __halves2half2(__float2half_rn(o0), __float2half_rn(o1));
                }
            }
        }
    }
}

// ---------------- fc2 GEMM: K=768, + res + res2 -> NCHW out ----------------
__global__ __launch_bounds__(512) void mma_gemm6(
    const __half* __restrict__ A, const __half* __restrict__ B,
    const float* __restrict__ bias, const __half* __restrict__ resh,
    const __half* __restrict__ res2h, float* __restrict__ Cf, int K)
{
    extern __shared__ __align__(16) char dsm[];
    const uint32_t s0 = smem_u32(dsm);
    const int t = threadIdx.x, wid = t >> 5, lane = t & 31;
    const int m0 = blockIdx.x * 128;
    const int wm = (wid >> 2) * 32, wn = (wid & 3) * 48;
    const int mat = lane >> 3, rr = lane & 7;
    const int kc = K >> 5;

    float acc[2][6][4];
    #pragma unroll
    for (int i = 0; i < 2; i++)
        #pragma unroll
        for (int j = 0; j < 6; j++)
            #pragma unroll
            for (int l = 0; l < 4; l++) acc[i][j][l] = 0.f;

    auto issue = [&](int c) {
        const int buf = c % STG;
        const uint32_t aS = s0 + buf*ASTAGE;
        const uint32_t bS = s0 + STG*ASTAGE + buf*BSTAGE;
        const int ac = c << 5;
        {
            const int row = t >> 2, seg = t & 3;
            CPA16(aS + row*AROWB + seg*16,
                  A + (size_t)(m0 + row)*K + ac + seg*8);
        }
        {
            const int row = t >> 2, seg = t & 3;
            CPA16(bS + row*BROWB + seg*16,
                  B + (size_t)(row)*K + ac + seg*8);
            if (t < 256) {
                const int idx = t + 512, row2 = idx >> 2, seg2 = idx & 3;
                CPA16(bS + row2*BROWB + seg2*16,
                      B + (size_t)(row2)*K + ac + seg2*8);
            }
        }
    };

    #pragma unroll
    for (int p = 0; p < 3; p++) {
        if (p < kc) issue(p);
        CPCOMMIT();
    }
    for (int c = 0; c < kc; c++) {
        CPWAIT(2);
        __syncthreads();
        if (c + 3 < kc) issue(c + 3);
        CPCOMMIT();
        const int buf = c % STG;
        const uint32_t aB = s0 + buf*ASTAGE;
        const uint32_t bB = s0 + STG*ASTAGE + buf*BSTAGE;
        #pragma unroll
        for (int ks = 0; ks < 2; ks++) {
            const int kb = ks * 32;
            uint32_t afr[2][4];
            #pragma unroll
            for (int am = 0; am < 2; am++)
                LDMX4(afr[am], aB + (uint32_t)((wm + am*16 + (lane & 15))*AROWB)
                             + kb + ((lane >> 4) << 4));
            uint32_t bf[3][4];
            #pragma unroll
            for (int bn = 0; bn < 3; bn++)
                LDMX4(bf[bn], bB + (uint32_t)((wn + bn*16 + ((mat & 2) << 2) + rr)*BROWB)
                            + kb + ((mat & 1) << 4));
            #pragma unroll
            for (int am = 0; am < 2; am++)
                #pragma unroll
                for (int bn = 0; bn < 3; bn++) {
                    MMA16816(acc[am][bn*2],   afr[am], bf[bn][0], bf[bn][1]);
                    MMA16816(acc[am][bn*2+1], afr[am], bf[bn][2], bf[bn][3]);
                }
        }
    }

    #pragma unroll
    for (int am = 0; am < 2; am++) {
        #pragma unroll
        for (int nf = 0; nf < 6; nf++) {
            const int nn = wn + nf*8 + ((lane & 3) << 1);
            const float b0 = bias[nn], b1 = bias[nn + 1];
            #pragma unroll
            for (int h = 0; h < 2; h++) {
                const int m = m0 + wm + am*16 + (lane >> 2) + h*8;
                float2 r1 = __half22float2(*(const __half2*)(resh + (size_t)m*CDIM + nn));
                float2 r2 = __half22float2(*(const __half2*)(res2h + (size_t)m*CDIM + nn));
                float o0 = acc[am][nf][h*2]     + b0 + r1.x + r2.x;
                float o1 = acc[am][nf][h*2 + 1] + b1 + r1.y + r2.y;
                const int bb = m / L, hw = m - bb*L;
                Cf[((size_t)bb*CDIM + nn)*L + hw]     = o0;
                Cf[((size_t)bb*CDIM + nn + 1)*L + hw] = o1;
            }
        }
    }
}

// ---------------- fused prep: NHWC convert + weight converts + rel-pos bias -------
#define NB_X  896
#define W_C1 (CDIM*KCONV)
#define W_C2 (W_C1 + 3*CDIM*CDIM)
#define W_C3 (W_C2 + CDIM*CDIM)
#define W_C4 (W_C3 + 4*CDIM*CDIM)
#define W_C5 (W_C4 + CDIM*4*CDIM)
#define NB_W 2160
#define NB_B 84
__global__ void prep_all(const float* __restrict__ x, __half* __restrict__ xh,
                         const float* __restrict__ w0, __half* __restrict__ d0,
                         const float* __restrict__ w1, __half* __restrict__ d1,
                         const float* __restrict__ w2, __half* __restrict__ d2,
                         const float* __restrict__ w3, __half* __restrict__ d3,
                         const float* __restrict__ w4, __half* __restrict__ d4,
                         const float* __restrict__ tab, const int* __restrict__ idx,
                         float* __restrict__ biasout)
{
    const int bid = blockIdx.x;
    if (bid < NB_X) {
        __shared__ float tile[CIN][WDIM + 1];
        const int b = bid / HDIM, h = bid - b*HDIM;
        for (int i = threadIdx.x; i < CIN*WDIM; i += 256) {
            int c = i / WDIM, w = i - c*WDIM;
            tile[c][w] = x[((size_t)(b*CIN + c)*HDIM + h)*WDIM + w];
        }
        __syncthreads();
        for (int i = threadIdx.x; i < WDIM*8; i += 256) {
            int w = i >> 3, cs = (i & 7)*8;
            __half v[8];
            #pragma unroll
            for (int u = 0; u < 8; u++) v[u] = __float2half_rn(tile[cs + u][w]);
            *(uint4*)(xh + (((size_t)(b*HDIM + h)*WDIM + w) << 6) + cs) = *(uint4*)v;
        }
    } else if (bid < NB_X + NB_W) {
        int i = (bid - NB_X)*256 + threadIdx.x;
        if (i < W_C1) {
            int n = i / KCONV, k = i - n*KCONV;
            int ci = k / 9, r = k - ci*9;
            d0[n*KCONV + r*64 + ci] = __float2half_rn(w0[i]);
        } else if (i < W_C5) {
            const float* s; __half* d; int off;
            if      (i < W_C2) { s = w1; d = d1; off = W_C1; }
            else if (i < W_C3) { s = w2; d = d2; off = W_C2; }
            else if (i < W_C4) { s = w3; d = d3; off = W_C3; }
            else               { s = w4; d = d4; off = W_C4; }
            d[i - off] = __float2half_rn(s[i - off]);
        }
    } else {
        int i = (bid - NB_X - NB_W)*256 + threadIdx.x;
        if (i < NH*64*56) {
            int h = i / (64*56), rem = i % (64*56);
            int r = rem / 56, c = rem % 56;
            float v;
            if (c >= NWIN)      v = -1e30f;
            else if (r >= NWIN) v = 0.f;
            else                v = tab[idx[r*NWIN + c]*NH + h];
            biasout[i] = v;
        }
    }
}

// ---------------- HMMA window attention (cp.async loads) ----------------
#define QROW 200
#define SM_QS  256
#define SM_KS  (SM_QS + 64*400)
#define SM_VS  (SM_KS + 64*400)
#define SMEM_ATT (SM_VS + 64*400)   // 77056
__global__ __launch_bounds__(384, 2) void attn_mma(const __half* __restrict__ qkv,
                                                   const float* __restrict__ biasp,
                                                   __half* __restrict__ o)
{
    extern __shared__ __align__(16) char sm[];
    int* toks = (int*)sm;
    __half* QS = (__half*)(sm + SM_QS);
    __half* KS = (__half*)(sm + SM_KS);
    __half* VS = (__half*)(sm + SM_VS);
    const int t = threadIdx.x, wid = t >> 5, lane = t & 31;
    const int wi = blockIdx.x;
    const int b = wi >> 8, r_ = wi & 255, wh = r_ >> 4, ww = r_ & 15;
    if (t < NWIN) toks[t] = b*L + (wh*WS + t/WS)*WDIM + (ww*WS + t%WS);
    __syncthreads();

    const uint32_t qsB = smem_u32(QS), ksB = smem_u32(KS), vsB = smem_u32(VS);

    for (int idx = t; idx < NWIN*24; idx += 384) {
        int p = idx / 24, seg = idx % 24;
        const __half* src = qkv + (size_t)toks[p]*576 + seg*8;
        CPA16(qsB + p*400 + seg*16, src);
        CPA16(ksB + p*400 + seg*16, src + 192);
        CPA16(vsB + p*400 + seg*16, src + 384);
    }
    for (int idx = t; idx < 15*24; idx += 384) {
        int rr2 = idx / 24, seg = idx % 24;
        uint4 z = make_uint4(0,0,0,0);
        *(uint4*)(QS + (NWIN + rr2)*QROW + seg*8) = z;
        *(uint4*)(KS + (NWIN + rr2)*QROW + seg*8) = z;
        *(uint4*)(VS + (NWIN + rr2)*QROW + seg*8) = z;
    }
    CPCOMMIT();
    CPWAIT(0);
    __syncthreads();

    const int h = wid >> 1, m0 = (wid & 1)*32;
    const int mat = lane >> 3, rr = lane & 7;

    float accS[2][7][4];
    #pragma unroll
    for (int i = 0; i < 2; i++)
        #pragma unroll
        for (int j = 0; j < 7; j++)
            #pragma unroll
            for (int l = 0; l < 4; l++) accS[i][j][l] = 0.f;
    #pragma unroll
    for (int ks = 0; ks < 2; ks++) {
        const int kb = ks*32;
        uint32_t af[2][4];
        #pragma unroll
        for (int mf = 0; mf < 2; mf++)
            LDMX4(af[mf], qsB + (uint32_t)((m0 + mf*16 + (lane & 15))*400)
                        + h*64 + kb + ((lane >> 4) << 4));
        uint32_t bf[4][4];
        #pragma unroll
        for (int bn = 0; bn < 4; bn++)
            LDMX4(bf[bn], ksB + (uint32_t)((bn*16 + ((mat & 2) << 2) + rr)*400)
                        + h*64 + kb + ((mat & 1) << 4));
        #pragma unroll
        for (int mf = 0; mf < 2; mf++)
            #pragma unroll
            for (int nf = 0; nf < 7; nf++)
                MMA16816(accS[mf][nf], af[mf], bf[nf >> 1][(nf & 1)*2], bf[nf >> 1][(nf & 1)*2 + 1]);
    }

    const float scale = 0.17677669529663687f;
    #pragma unroll
    for (int mf = 0; mf < 2; mf++) {
        const int rl = m0 + mf*16 + (lane >> 2);
        const float* b0 = biasp + (h*64 + rl)*56;
        const float* b1 = biasp + (h*64 + rl + 8)*56;
        #pragma unroll
        for (int nf = 0; nf < 7; nf++) {
            const int c0 = nf*8 + (lane & 3)*2;
            float2 blo = *(const float2*)(b0 + c0);
            float2 bhi = *(const float2*)(b1 + c0);
            accS[mf][nf][0] = accS[mf][nf][0]*scale + blo.x;
            accS[mf][nf][1] = accS[mf][nf][1]*scale + blo.y;
            accS[mf][nf][2] = accS[mf][nf][2]*scale + bhi.x;
            accS[mf][nf][3] = accS[mf][nf][3]*scale + bhi.y;
        }
        float mlo = -1e30f, mhi = -1e30f;
        #pragma unroll
        for (int nf = 0; nf < 7; nf++) {
            mlo = fmaxf(mlo, fmaxf(accS[mf][nf][0], accS[mf][nf][1]));
            mhi = fmaxf(mhi, fmaxf(accS[mf][nf][2], accS[mf][nf][3]));
        }
        #pragma unroll
        for (int ox = 1; ox < 4; ox <<= 1) {
            mlo = fmaxf(mlo, __shfl_xor_sync(0xffffffffu, mlo, ox));
            mhi = fmaxf(mhi, __shfl_xor_sync(0xffffffffu, mhi, ox));
        }
        float slo = 0.f, shi = 0.f;
        #pragma unroll
        for (int nf = 0; nf < 7; nf++) {
            accS[mf][nf][0] = __expf(accS[mf][nf][0] - mlo);
            accS[mf][nf][1] = __expf(accS[mf][nf][1] - mlo);
            accS[mf][nf][2] = __expf(accS[mf][nf][2] - mhi);
            accS[mf][nf][3] = __expf(accS[mf][nf][3] - mhi);
            slo += accS[mf][nf][0] + accS[mf][nf][1];
            shi += accS[mf][nf][2] + accS[mf][nf][3];
        }
        #pragma unroll
        for (int ox = 1; ox < 4; ox <<= 1) {
            slo += __shfl_xor_sync(0xffffffffu, slo, ox);
            shi += __shfl_xor_sync(0xffffffffu, shi, ox);
        }
        const float ilo = 1.f/slo, ihi = 1.f/shi;
        #pragma unroll
        for (int nf = 0; nf < 7; nf++) {
            accS[mf][nf][0] *= ilo; accS[mf][nf][1] *= ilo;
            accS[mf][nf][2] *= ihi; accS[mf][nf][3] *= ihi;
        }
    }

    float accO[2][4][4];
    #pragma unroll
    for (int i = 0; i < 2; i++)
        #pragma unroll
        for (int j = 0; j < 4; j++)
            #pragma unroll
            for (int l = 0; l < 4; l++) accO[i][j][l] = 0.f;
    #pragma unroll
    for (int kt = 0; kt < 4; kt++) {
        uint32_t bf[2][4];
        #pragma unroll
        for (int bn = 0; bn < 2; bn++)
            LDMX4T(bf[bn], vsB + (uint32_t)((kt*16 + ((mat & 1) << 3) + rr)*400)
                         + h*64 + bn*32 + ((mat & 2) << 3));
        #pragma unroll
        for (int mf = 0; mf < 2; mf++) {
            const int nf0 = 2*kt, nf1 = 2*kt + 1;
            uint32_t a0 = packh2(accS[mf][nf0][0], accS[mf][nf0][1]);
            uint32_t a1 = packh2(accS[mf][nf0][2], accS[mf][nf0][3]);
            uint32_t a2 = 0, a3 = 0;
            if (nf1 < 7) {
                a2 = packh2(accS[mf][nf1][0], accS[mf][nf1][1]);
                a3 = packh2(accS[mf][nf1][2], accS[mf][nf1][3]);
            }
            #pragma unroll
            for (int nf = 0; nf < 4; nf++)
                MMA16816R(accO[mf][nf], a0, a1, a2, a3,
                          bf[nf >> 1][(nf & 1)*2], bf[nf >> 1][(nf & 1)*2 + 1]);
        }
    }

    #pragma unroll
    for (int mf = 0; mf < 2; mf++) {
        const int rl = m0 + mf*16 + (lane >> 2);
        #pragma unroll
        for (int nf = 0; nf < 4; nf++) {
            const int c = nf*8 + (lane & 3)*2;
            if (rl < NWIN)
                *(__half2*)(o + (size_t)toks[rl]*CDIM + h*HD + c) =
                    __halves2half2(__float2half_rn(accO[mf][nf][0]),
                                   __float2half_rn(accO[mf][nf][1]));
            if (rl + 8 < NWIN)
                *(__half2*)(o + (size_t)toks[rl + 8]*CDIM + h*HD + c) =
                    __halves2half2(__float2half_rn(accO[mf][nf][2]),
                                   __float2half_rn(accO[mf][nf][3]));
        }
    }
}

// ---------------- launch ----------------
extern "C" void kernel_launch(void* const* d_in, const int* in_sizes, int n_in,
                              void* d_out, int out_size)
{
    const float* x        = (const float*)d_in[0];
    const float* proj_w   = (const float*)d_in[1];
    const float* proj_b   = (const float*)d_in[2];
    const float* ln1_w    = (const float*)d_in[3];
    const float* ln1_b    = (const float*)d_in[4];
    const float* qkv_w    = (const float*)d_in[5];
    const float* qkv_b    = (const float*)d_in[6];
    const float* rel_tab  = (const float*)d_in[7];
    const float* apw      = (const float*)d_in[8];
    const float* apb      = (const float*)d_in[9];
    const float* ln2_w    = (const float*)d_in[10];
    const float* ln2_b    = (const float*)d_in[11];
    const float* fc1_w    = (const float*)d_in[12];
    const float* fc1_b    = (const float*)d_in[13];
    const float* fc2_w    = (const float*)d_in[14];
    const float* fc2_b    = (const float*)d_in[15];
    const int*   rel_idx  = (const int*)d_in[16];
    float* out = (float*)d_out;

    __half *xhp, *aoh, *m1h, *qkvh, *xth, *t1h, *wconv, *wqkv, *wap, *wfc1, *wfc2;
    float *biasp;
    cudaGetSymbolAddress((void**)&xhp,   g_xh);
    cudaGetSymbolAddress((void**)&aoh,   g_ao);
    cudaGetSymbolAddress((void**)&m1h,   g_m1);
    cudaGetSymbolAddress((void**)&qkvh,  g_qkv);
    cudaGetSymbolAddress((void**)&xth,   g_xt);
    cudaGetSymbolAddress((void**)&t1h,   g_t1);
    cudaGetSymbolAddress((void**)&biasp, g_bias);
    cudaGetSymbolAddress((void**)&wconv, g_wconv);
    cudaGetSymbolAddress((void**)&wqkv,  g_wqkv);
    cudaGetSymbolAddress((void**)&wap,   g_wap);
    cudaGetSymbolAddress((void**)&wfc1,  g_wfc1);
    cudaGetSymbolAddress((void**)&wfc2,  g_wfc2);

    cudaFuncSetAttribute((const void*)fused_gemm<3,3,0>, cudaFuncAttributeMaxDynamicSharedMemorySize, SMEM_FUSE);
    cudaFuncSetAttribute((const void*)fused_gemm<4,4,2>, cudaFuncAttributeMaxDynamicSharedMemorySize, SMEM_FUSE);
    cudaFuncSetAttribute((const void*)mma_gemm6, cudaFuncAttributeMaxDynamicSharedMemorySize, SMEM_GEMM);
    cudaFuncSetAttribute((const void*)attn_mma,  cudaFuncAttributeMaxDynamicSharedMemorySize, SMEM_ATT);

    const int MB = TKN/128;   // 784

    prep_all<<<NB_X + NB_W + NB_B, 256>>>(x, xhp,
                                          proj_w, wconv, qkv_w, wqkv, apw, wap,
                                          fc1_w, wfc1, fc2_w, wfc2,
                                          rel_tab, rel_idx, biasp);
    // conv(implicit) + LN1 + qkv  (one kernel)
    fused_gemm<3,3,0><<<MB, 512, SMEM_FUSE>>>(xhp, wconv, proj_b, nullptr,
                                              ln1_w, ln1_b, xth,
                                              wqkv, qkv_b, qkvh, KCONV);
    attn_mma<<<NWTOT, 384, SMEM_ATT>>>(qkvh, biasp, aoh);
    // attn-proj + residual(xt) + LN2 + fc1 + GELU  (one kernel)
    fused_gemm<4,4,2><<<MB, 512, SMEM_FUSE>>>(aoh, wap, apb, xth,
                                              ln2_w, ln2_b, t1h,
                                              wfc1, fc1_b, m1h, CDIM);
    // fc2 + residual(t1) + shortcut(xt) -> NCHW out
    mma_gemm6<<<MB, 512, SMEM_GEMM>>>(m1h, wfc2, fc2_b, t1h, xth, out, 4*CDIM);
}